// round 11
// baseline (speedup 1.0000x reference)
#include <cuda_runtime.h>
#include <cuda_fp16.h>
#include <cstdint>

#define N_NODES 100000
#define N_EDGES 1600000
#define D 128

#define SCAN_B 1024
#define NBLK1  ((N_NODES + SCAN_B - 1) / SCAN_B)   // 98

// padded row stride for smem tiles (fp16 elems): conflict-free fragment loads
#define TSTRIDE 136
#define TILE_U4 2304            // 128*136*2B/16 = 2176, padded for copy loop

// ---- static device scratch (no allocs allowed) ----
__device__ __half2 g_hh[(size_t)N_NODES * 64];   // h in fp16 (25.6 MB)
__device__ int   g_cnt[N_NODES];               // histogram, then cursor
__device__ int   g_off[N_NODES + 1];           // CSR row offsets
__device__ int   g_bsum[SCAN_B];               // scan block sums
__device__ int2  g_spair[N_EDGES];             // row-sorted (col, val-bits)
__device__ uint4 g_wT[TILE_U4];                // w^T fp16(rn), padded [128][136]

// ---- host-side stream/event handles (created before harness mem checkpoint) ----
struct ForkJoin {
    cudaStream_t s2;
    cudaEvent_t evFork, evJoin;
    ForkJoin() {
        cudaStreamCreateWithFlags(&s2, cudaStreamNonBlocking);
        cudaEventCreateWithFlags(&evFork, cudaEventDisableTiming);
        cudaEventCreateWithFlags(&evJoin, cudaEventDisableTiming);
    }
};
static ForkJoin g_fj;

// ===========================================================================
// Prep: w -> fp16 (round-nearest), transposed (Bt[n][k] = w[k][n]), padded.
// ===========================================================================
__global__ void wprep_kernel(const float* __restrict__ w) {
    int idx = blockIdx.x * 256 + threadIdx.x;   // 0..16383
    int k = idx >> 7, n = idx & 127;
    ((__half*)g_wT)[n * TSTRIDE + k] = __float2half_rn(w[idx]);
}

// ===========================================================================
// mma.sync fp16 GEMM (A 2-split): h = (x*mask) @ w   -> fp16 output
// CTA: 128 rows x 128 cols x K=128. 8 warps in 4x2 grid, warp tile 32x64.
// smem 104KB -> 2 CTAs/SM.
// ===========================================================================
__device__ __forceinline__ void mma16816(float* d, const uint32_t* a, const uint32_t* b) {
    asm volatile(
        "mma.sync.aligned.m16n8k16.row.col.f32.f16.f16.f32 "
        "{%0,%1,%2,%3}, {%4,%5,%6,%7}, {%8,%9}, {%0,%1,%2,%3};"
        : "+f"(d[0]), "+f"(d[1]), "+f"(d[2]), "+f"(d[3])
        : "r"(a[0]), "r"(a[1]), "r"(a[2]), "r"(a[3]), "r"(b[0]), "r"(b[1]));
}

#define SM_A_HI 0
#define SM_A_LO 34816
#define SM_B    69632
// B region must hold the full padded copy: 2304 uint4 = 36864 bytes
#define SM_TOTAL_G (69632 + 36864)   // 106496

__global__ __launch_bounds__(256, 2)
void gemm_mma_kernel(const float* __restrict__ x,
                     const float* __restrict__ mask,
                     __half2* __restrict__ hh) {
    extern __shared__ char smem[];
    const int tid = threadIdx.x;
    const int wid = tid >> 5;
    const int lane = tid & 31;
    const int wr = wid >> 1;          // warp row 0..3 -> rows wr*32..+32
    const int wc = wid & 1;           // warp col 0..1 -> cols wc*64..+64
    const int g = lane >> 2;          // group 0..7
    const int t = lane & 3;           // thread-in-group
    const int rowBase = blockIdx.x * 128;

    // ---- B tile: linear copy of prebuilt padded image ----
#pragma unroll
    for (int i = 0; i < 9; i++) {
        int idx = tid + i * 256;      // 0..2303 (tail reads padding)
        ((uint4*)(smem + SM_B))[idx] = g_wT[idx];
    }

    // ---- A tiles: load x*mask, split fp16 hi/lo, store padded row-major ----
#pragma unroll
    for (int i = 0; i < 16; i++) {
        int idx = tid + i * 256;      // 0..4095
        int row = idx >> 5;           // 0..127
        int c4 = (idx & 31) << 2;     // 0,4,...,124
        int grow = rowBase + row;
        float f0 = 0.f, f1 = 0.f, f2 = 0.f, f3 = 0.f;
        if (grow < N_NODES) {
            const float4 xv = *(const float4*)(x    + (size_t)grow * D + c4);
            const float4 mv = *(const float4*)(mask + (size_t)grow * D + c4);
            f0 = xv.x * mv.x; f1 = xv.y * mv.y; f2 = xv.z * mv.z; f3 = xv.w * mv.w;
        }
        __half h0 = __float2half_rn(f0), h1 = __float2half_rn(f1);
        __half h2 = __float2half_rn(f2), h3 = __float2half_rn(f3);
        __half l0 = __float2half_rn(f0 - __half2float(h0));
        __half l1 = __float2half_rn(f1 - __half2float(h1));
        __half l2 = __float2half_rn(f2 - __half2float(h2));
        __half l3 = __float2half_rn(f3 - __half2float(h3));
        int off = (row * TSTRIDE + c4) * 2;       // bytes
        *(__half2*)(smem + SM_A_HI + off)     = __halves2half2(h0, h1);
        *(__half2*)(smem + SM_A_HI + off + 4) = __halves2half2(h2, h3);
        *(__half2*)(smem + SM_A_LO + off)     = __halves2half2(l0, l1);
        *(__half2*)(smem + SM_A_LO + off + 4) = __halves2half2(l2, l3);
    }
    __syncthreads();

    float acc[2][8][4];
#pragma unroll
    for (int mt = 0; mt < 2; mt++)
#pragma unroll
        for (int nt = 0; nt < 8; nt++)
#pragma unroll
            for (int q = 0; q < 4; q++) acc[mt][nt][q] = 0.f;

#pragma unroll
    for (int ks = 0; ks < 8; ks++) {
        const int kb = ks * 16 + 2 * t;           // element col for frag reg 0

        uint32_t ah[2][4], al[2][4], bf[8][2];
#pragma unroll
        for (int mt = 0; mt < 2; mt++) {
            const int r = wr * 32 + mt * 16 + g;
            const int o00 = (r * TSTRIDE + kb) * 2;
            const int o10 = ((r + 8) * TSTRIDE + kb) * 2;
            ah[mt][0] = *(const uint32_t*)(smem + SM_A_HI + o00);
            ah[mt][1] = *(const uint32_t*)(smem + SM_A_HI + o10);
            ah[mt][2] = *(const uint32_t*)(smem + SM_A_HI + o00 + 16);
            ah[mt][3] = *(const uint32_t*)(smem + SM_A_HI + o10 + 16);
            al[mt][0] = *(const uint32_t*)(smem + SM_A_LO + o00);
            al[mt][1] = *(const uint32_t*)(smem + SM_A_LO + o10);
            al[mt][2] = *(const uint32_t*)(smem + SM_A_LO + o00 + 16);
            al[mt][3] = *(const uint32_t*)(smem + SM_A_LO + o10 + 16);
        }
#pragma unroll
        for (int nt = 0; nt < 8; nt++) {
            const int n = wc * 64 + nt * 8 + g;
            const int o = (n * TSTRIDE + kb) * 2;
            bf[nt][0] = *(const uint32_t*)(smem + SM_B + o);
            bf[nt][1] = *(const uint32_t*)(smem + SM_B + o + 16);
        }

#pragma unroll
        for (int mt = 0; mt < 2; mt++)
#pragma unroll
            for (int nt = 0; nt < 8; nt++)
                mma16816(acc[mt][nt], ah[mt], bf[nt]);
#pragma unroll
        for (int mt = 0; mt < 2; mt++)
#pragma unroll
            for (int nt = 0; nt < 8; nt++)
                mma16816(acc[mt][nt], al[mt], bf[nt]);
    }

    // ---- epilogue: fp16 stores (halves gather traffic downstream) ----
#pragma unroll
    for (int mt = 0; mt < 2; mt++) {
        const int r0 = rowBase + wr * 32 + mt * 16 + g;
#pragma unroll
        for (int nt = 0; nt < 8; nt++) {
            const int col2 = wc * 32 + nt * 4 + t;     // half2 index in row (64 per row)
            if (r0 < N_NODES)
                hh[(size_t)r0 * 64 + col2] = __floats2half2_rn(acc[mt][nt][0], acc[mt][nt][1]);
            if (r0 + 8 < N_NODES)
                hh[(size_t)(r0 + 8) * 64 + col2] = __floats2half2_rn(acc[mt][nt][2], acc[mt][nt][3]);
        }
    }
}

// ---------------------------------------------------------------------------
// CSR build: histogram -> scan -> pair scatter
// ---------------------------------------------------------------------------
__global__ void zero_cnt_kernel() {
    int i = blockIdx.x * blockDim.x + threadIdx.x;
    if (i < N_NODES) g_cnt[i] = 0;
}

__global__ void hist_kernel(const int* __restrict__ erow) {
    int e = blockIdx.x * blockDim.x + threadIdx.x;
    if (e < N_EDGES) atomicAdd(&g_cnt[erow[e]], 1);
}

__global__ __launch_bounds__(SCAN_B)
void scan1_kernel() {
    __shared__ int s[SCAN_B];
    int tid = threadIdx.x;
    int gid = blockIdx.x * SCAN_B + tid;
    int v = (gid < N_NODES) ? g_cnt[gid] : 0;
    s[tid] = v;
    __syncthreads();
#pragma unroll
    for (int off = 1; off < SCAN_B; off <<= 1) {
        int t = (tid >= off) ? s[tid - off] : 0;
        __syncthreads();
        s[tid] += t;
        __syncthreads();
    }
    if (gid < N_NODES) g_off[gid] = s[tid] - v;     // exclusive
    if (tid == SCAN_B - 1) g_bsum[blockIdx.x] = s[tid];
}

__global__ __launch_bounds__(128)
void scan2_kernel() {
    __shared__ int s[128];
    int tid = threadIdx.x;
    int v = (tid < NBLK1) ? g_bsum[tid] : 0;
    s[tid] = v;
    __syncthreads();
#pragma unroll
    for (int off = 1; off < 128; off <<= 1) {
        int t = (tid >= off) ? s[tid - off] : 0;
        __syncthreads();
        s[tid] += t;
        __syncthreads();
    }
    g_bsum[tid] = s[tid] - v;                       // exclusive
}

__global__ void scan3_kernel() {
    int i = blockIdx.x * blockDim.x + threadIdx.x;
    if (i < N_NODES) {
        g_off[i] += g_bsum[i >> 10];
        g_cnt[i] = 0;
    }
    if (i == 0) g_off[N_NODES] = N_EDGES;
}

__global__ void scatter_pairs_kernel(const int* __restrict__ erow,
                                     const int* __restrict__ ecol,
                                     const float* __restrict__ evl) {
    int e = blockIdx.x * blockDim.x + threadIdx.x;
    if (e >= N_EDGES) return;
    int r = erow[e];
    int p = g_off[r] + atomicAdd(&g_cnt[r], 1);
    g_spair[p] = make_int2(ecol[e], __float_as_int(evl[e]));
}

// ---------------------------------------------------------------------------
// Aggregation: warp per row, fp16 gather + fp32 accumulate, fused bias+relu.
// Gather traffic halved vs fp32 h (256B/edge). Unroll x4 for MLP.
// ---------------------------------------------------------------------------
__device__ __forceinline__ void acc_edge(float4& acc, const uint2 u, const float v) {
    const float2 f0 = __half22float2(*(const __half2*)&u.x);
    const float2 f1 = __half22float2(*(const __half2*)&u.y);
    acc.x = fmaf(f0.x, v, acc.x);
    acc.y = fmaf(f0.y, v, acc.y);
    acc.z = fmaf(f1.x, v, acc.z);
    acc.w = fmaf(f1.y, v, acc.w);
}

__global__ __launch_bounds__(256)
void agg_kernel(const __half2* __restrict__ hh,
                const float* __restrict__ b,
                float4* __restrict__ out) {
    const int r = blockIdx.x * 8 + (threadIdx.x >> 5);
    const int lane = threadIdx.x & 31;
    if (r >= N_NODES) return;

    const int s  = g_off[r];
    const int e2 = g_off[r + 1];
    const uint2* __restrict__ h8 = (const uint2*)hh;   // 4 halves per lane

    float4 acc = make_float4(0.f, 0.f, 0.f, 0.f);
    int t = s;
    for (; t + 3 < e2; t += 4) {
        const int2 p0 = g_spair[t];
        const int2 p1 = g_spair[t + 1];
        const int2 p2 = g_spair[t + 2];
        const int2 p3 = g_spair[t + 3];
        const uint2 a0 = h8[(size_t)p0.x * 32 + lane];
        const uint2 a1 = h8[(size_t)p1.x * 32 + lane];
        const uint2 a2 = h8[(size_t)p2.x * 32 + lane];
        const uint2 a3 = h8[(size_t)p3.x * 32 + lane];
        acc_edge(acc, a0, __int_as_float(p0.y));
        acc_edge(acc, a1, __int_as_float(p1.y));
        acc_edge(acc, a2, __int_as_float(p2.y));
        acc_edge(acc, a3, __int_as_float(p3.y));
    }
    for (; t < e2; t++) {
        const int2 p0 = g_spair[t];
        const uint2 a0 = h8[(size_t)p0.x * 32 + lane];
        acc_edge(acc, a0, __int_as_float(p0.y));
    }

    const float4 bv = ((const float4*)b)[lane];
    acc.x = fmaxf(acc.x + bv.x, 0.f);
    acc.y = fmaxf(acc.y + bv.y, 0.f);
    acc.z = fmaxf(acc.z + bv.z, 0.f);
    acc.w = fmaxf(acc.w + bv.w, 0.f);
    out[(size_t)r * 32 + lane] = acc;
}

// ---------------------------------------------------------------------------
extern "C" void kernel_launch(void* const* d_in, const int* in_sizes, int n_in,
                              void* d_out, int out_size) {
    const float* x    = (const float*)d_in[0];   // [N, 128]
    const float* w    = (const float*)d_in[1];   // [128, 128]
    const float* b    = (const float*)d_in[2];   // [128]
    const int*   erow = (const int*)  d_in[3];   // [E]
    const int*   ecol = (const int*)  d_in[4];   // [E]
    const float* evl  = (const float*)d_in[5];   // [E]
    const float* mask = (const float*)d_in[6];   // [N, 128]
    float* out = (float*)d_out;                  // [N, 128]

    __half2* hh;
    cudaGetSymbolAddress((void**)&hh, g_hh);

    cudaFuncSetAttribute(gemm_mma_kernel,
                         cudaFuncAttributeMaxDynamicSharedMemorySize, SM_TOTAL_G);

    // ---- fork: GEMM path on side stream, CSR build on main stream ----
    cudaEventRecord(g_fj.evFork, 0);
    cudaStreamWaitEvent(g_fj.s2, g_fj.evFork, 0);

    // 1) w prep, then tensor-core GEMM  [side stream]
    wprep_kernel<<<64, 256, 0, g_fj.s2>>>(w);
    gemm_mma_kernel<<<(N_NODES + 127) / 128, 256, SM_TOTAL_G, g_fj.s2>>>(x, mask, hh);

    // 2) CSR build  [main stream, concurrent]
    zero_cnt_kernel<<<(N_NODES + 255) / 256, 256>>>();
    hist_kernel<<<(N_EDGES + 255) / 256, 256>>>(erow);
    scan1_kernel<<<NBLK1, SCAN_B>>>();
    scan2_kernel<<<1, 128>>>();
    scan3_kernel<<<(N_NODES + 255) / 256, 256>>>();
    scatter_pairs_kernel<<<(N_EDGES + 255) / 256, 256>>>(erow, ecol, evl);

    // ---- join: agg needs both h and the CSR ----
    cudaEventRecord(g_fj.evJoin, g_fj.s2);
    cudaStreamWaitEvent(0, g_fj.evJoin, 0);

    // 3) aggregate + bias + relu (writes all of d_out)
    agg_kernel<<<(N_NODES + 7) / 8, 256>>>(hh, b, (float4*)out);
}

// round 13
// speedup vs baseline: 1.1883x; 1.1883x over previous
#include <cuda_runtime.h>
#include <cuda_fp16.h>
#include <cstdint>

#define N_NODES 100000
#define N_EDGES 1600000
#define D 128

#define SCAN_B 1024
#define NBLK1  ((N_NODES + SCAN_B - 1) / SCAN_B)   // 98

// padded row stride for smem tiles (fp16 elems): conflict-free fragment loads
#define TSTRIDE 136
#define TILE_U4 2304            // 128*136*2B/16 = 2176, padded for copy loop

// ---- static device scratch (no allocs allowed) ----
__device__ float g_h[(size_t)N_NODES * D];     // h = (x*mask)@w   (51.2 MB, fp32)
__device__ int   g_cnt[N_NODES];               // histogram, then cursor
__device__ int   g_off[N_NODES + 1];           // CSR row offsets
__device__ int   g_bsum[SCAN_B];               // scan block sums
__device__ int2  g_spair[N_EDGES];             // row-sorted (col, val-bits)
__device__ uint4 g_wT[TILE_U4];                // w^T fp16(rn), padded [128][136]

// ---- host-side stream/event handles (created before harness mem checkpoint) ----
struct ForkJoin {
    cudaStream_t s2;
    cudaEvent_t evFork, evJoin;
    ForkJoin() {
        cudaStreamCreateWithFlags(&s2, cudaStreamNonBlocking);
        cudaEventCreateWithFlags(&evFork, cudaEventDisableTiming);
        cudaEventCreateWithFlags(&evJoin, cudaEventDisableTiming);
    }
};
static ForkJoin g_fj;

// ===========================================================================
// Prep: w -> fp16 (round-nearest), transposed (Bt[n][k] = w[k][n]), padded.
// ===========================================================================
__global__ void wprep_kernel(const float* __restrict__ w) {
    int idx = blockIdx.x * 256 + threadIdx.x;   // 0..16383
    int k = idx >> 7, n = idx & 127;
    ((__half*)g_wT)[n * TSTRIDE + k] = __float2half_rn(w[idx]);
}

// ===========================================================================
// mma.sync fp16 GEMM (single A, single B): h = (x*mask) @ w
// CTA: 128 rows x 128 cols x K=128. 8 warps in 4x2 grid, warp tile 32x64.
// smem 70KB -> 3 CTAs/SM.
// ===========================================================================
__device__ __forceinline__ void mma16816(float* d, const uint32_t* a, const uint32_t* b) {
    asm volatile(
        "mma.sync.aligned.m16n8k16.row.col.f32.f16.f16.f32 "
        "{%0,%1,%2,%3}, {%4,%5,%6,%7}, {%8,%9}, {%0,%1,%2,%3};"
        : "+f"(d[0]), "+f"(d[1]), "+f"(d[2]), "+f"(d[3])
        : "r"(a[0]), "r"(a[1]), "r"(a[2]), "r"(a[3]), "r"(b[0]), "r"(b[1]));
}

#define SM_A    0
// B region must hold the full padded copy: 2304 uint4 = 36864 bytes
#define SM_B    34816
#define SM_TOTAL_G (34816 + 36864)   // 71680

__global__ __launch_bounds__(256, 3)
void gemm_mma_kernel(const float* __restrict__ x,
                     const float* __restrict__ mask,
                     float* __restrict__ h) {
    extern __shared__ char smem[];
    const int tid = threadIdx.x;
    const int wid = tid >> 5;
    const int lane = tid & 31;
    const int wr = wid >> 1;          // warp row 0..3 -> rows wr*32..+32
    const int wc = wid & 1;           // warp col 0..1 -> cols wc*64..+64
    const int g = lane >> 2;          // group 0..7
    const int t = lane & 3;           // thread-in-group
    const int rowBase = blockIdx.x * 128;

    // ---- B tile: linear copy of prebuilt padded image ----
#pragma unroll
    for (int i = 0; i < 9; i++) {
        int idx = tid + i * 256;      // 0..2303 (tail reads padding)
        ((uint4*)(smem + SM_B))[idx] = g_wT[idx];
    }

    // ---- A tile: load x*mask, fp16 round, store padded row-major ----
#pragma unroll
    for (int i = 0; i < 16; i++) {
        int idx = tid + i * 256;      // 0..4095
        int row = idx >> 5;           // 0..127
        int c4 = (idx & 31) << 2;     // 0,4,...,124
        int grow = rowBase + row;
        float f0 = 0.f, f1 = 0.f, f2 = 0.f, f3 = 0.f;
        if (grow < N_NODES) {
            const float4 xv = *(const float4*)(x    + (size_t)grow * D + c4);
            const float4 mv = *(const float4*)(mask + (size_t)grow * D + c4);
            f0 = xv.x * mv.x; f1 = xv.y * mv.y; f2 = xv.z * mv.z; f3 = xv.w * mv.w;
        }
        int off = (row * TSTRIDE + c4) * 2;       // bytes
        *(__half2*)(smem + SM_A + off)     = __floats2half2_rn(f0, f1);
        *(__half2*)(smem + SM_A + off + 4) = __floats2half2_rn(f2, f3);
    }
    __syncthreads();

    float acc[2][8][4];
#pragma unroll
    for (int mt = 0; mt < 2; mt++)
#pragma unroll
        for (int nt = 0; nt < 8; nt++)
#pragma unroll
            for (int q = 0; q < 4; q++) acc[mt][nt][q] = 0.f;

#pragma unroll
    for (int ks = 0; ks < 8; ks++) {
        const int kb = ks * 16 + 2 * t;           // element col for frag reg 0

        uint32_t af[2][4], bf[8][2];
#pragma unroll
        for (int mt = 0; mt < 2; mt++) {
            const int r = wr * 32 + mt * 16 + g;
            const int o00 = (r * TSTRIDE + kb) * 2;
            const int o10 = ((r + 8) * TSTRIDE + kb) * 2;
            af[mt][0] = *(const uint32_t*)(smem + SM_A + o00);
            af[mt][1] = *(const uint32_t*)(smem + SM_A + o10);
            af[mt][2] = *(const uint32_t*)(smem + SM_A + o00 + 16);
            af[mt][3] = *(const uint32_t*)(smem + SM_A + o10 + 16);
        }
#pragma unroll
        for (int nt = 0; nt < 8; nt++) {
            const int n = wc * 64 + nt * 8 + g;
            const int o = (n * TSTRIDE + kb) * 2;
            bf[nt][0] = *(const uint32_t*)(smem + SM_B + o);
            bf[nt][1] = *(const uint32_t*)(smem + SM_B + o + 16);
        }

#pragma unroll
        for (int mt = 0; mt < 2; mt++)
#pragma unroll
            for (int nt = 0; nt < 8; nt++)
                mma16816(acc[mt][nt], af[mt], bf[nt]);
    }

    // ---- epilogue: fp32 stores ----
#pragma unroll
    for (int mt = 0; mt < 2; mt++) {
        const int r0 = rowBase + wr * 32 + mt * 16 + g;
#pragma unroll
        for (int nt = 0; nt < 8; nt++) {
            const int col = wc * 64 + nt * 8 + 2 * t;
            if (r0 < N_NODES)
                *(float2*)(h + (size_t)r0 * D + col) = make_float2(acc[mt][nt][0], acc[mt][nt][1]);
            if (r0 + 8 < N_NODES)
                *(float2*)(h + (size_t)(r0 + 8) * D + col) = make_float2(acc[mt][nt][2], acc[mt][nt][3]);
        }
    }
}

// ---------------------------------------------------------------------------
// CSR build: histogram -> scan -> pair scatter
// ---------------------------------------------------------------------------
__global__ void zero_cnt_kernel() {
    int i = blockIdx.x * blockDim.x + threadIdx.x;
    if (i < N_NODES) g_cnt[i] = 0;
}

__global__ void hist_kernel(const int* __restrict__ erow) {
    int e = blockIdx.x * blockDim.x + threadIdx.x;
    if (e < N_EDGES) atomicAdd(&g_cnt[erow[e]], 1);
}

__global__ __launch_bounds__(SCAN_B)
void scan1_kernel() {
    __shared__ int s[SCAN_B];
    int tid = threadIdx.x;
    int gid = blockIdx.x * SCAN_B + tid;
    int v = (gid < N_NODES) ? g_cnt[gid] : 0;
    s[tid] = v;
    __syncthreads();
#pragma unroll
    for (int off = 1; off < SCAN_B; off <<= 1) {
        int t = (tid >= off) ? s[tid - off] : 0;
        __syncthreads();
        s[tid] += t;
        __syncthreads();
    }
    if (gid < N_NODES) g_off[gid] = s[tid] - v;     // exclusive
    if (tid == SCAN_B - 1) g_bsum[blockIdx.x] = s[tid];
}

__global__ __launch_bounds__(128)
void scan2_kernel() {
    __shared__ int s[128];
    int tid = threadIdx.x;
    int v = (tid < NBLK1) ? g_bsum[tid] : 0;
    s[tid] = v;
    __syncthreads();
#pragma unroll
    for (int off = 1; off < 128; off <<= 1) {
        int t = (tid >= off) ? s[tid - off] : 0;
        __syncthreads();
        s[tid] += t;
        __syncthreads();
    }
    g_bsum[tid] = s[tid] - v;                       // exclusive
}

__global__ void scan3_kernel() {
    int i = blockIdx.x * blockDim.x + threadIdx.x;
    if (i < N_NODES) {
        g_off[i] += g_bsum[i >> 10];
        g_cnt[i] = 0;
    }
    if (i == 0) g_off[N_NODES] = N_EDGES;
}

__global__ void scatter_pairs_kernel(const int* __restrict__ erow,
                                     const int* __restrict__ ecol,
                                     const float* __restrict__ evl) {
    int e = blockIdx.x * blockDim.x + threadIdx.x;
    if (e >= N_EDGES) return;
    int r = erow[e];
    int p = g_off[r] + atomicAdd(&g_cnt[r], 1);
    g_spair[p] = make_int2(ecol[e], __float_as_int(evl[e]));
}

// ---------------------------------------------------------------------------
// Aggregation: warp per row, fp32 gather + fp32 accumulate, fused bias+relu.
// Unroll x4 for memory-level parallelism against L2 latency.
// ---------------------------------------------------------------------------
__global__ __launch_bounds__(256)
void agg_kernel(const float* __restrict__ h,
                const float* __restrict__ b,
                float4* __restrict__ out) {
    const int r = blockIdx.x * 8 + (threadIdx.x >> 5);
    const int lane = threadIdx.x & 31;
    if (r >= N_NODES) return;

    const int s  = g_off[r];
    const int e2 = g_off[r + 1];
    const float4* __restrict__ h4 = (const float4*)h;

    float4 acc = make_float4(0.f, 0.f, 0.f, 0.f);
    int t = s;
    for (; t + 3 < e2; t += 4) {
        const int2 p0 = g_spair[t];
        const int2 p1 = g_spair[t + 1];
        const int2 p2 = g_spair[t + 2];
        const int2 p3 = g_spair[t + 3];
        const float4 a0 = h4[(size_t)p0.x * 32 + lane];
        const float4 a1 = h4[(size_t)p1.x * 32 + lane];
        const float4 a2 = h4[(size_t)p2.x * 32 + lane];
        const float4 a3 = h4[(size_t)p3.x * 32 + lane];
        const float v0 = __int_as_float(p0.y);
        const float v1 = __int_as_float(p1.y);
        const float v2 = __int_as_float(p2.y);
        const float v3 = __int_as_float(p3.y);
        acc.x = fmaf(a0.x, v0, fmaf(a1.x, v1, fmaf(a2.x, v2, fmaf(a3.x, v3, acc.x))));
        acc.y = fmaf(a0.y, v0, fmaf(a1.y, v1, fmaf(a2.y, v2, fmaf(a3.y, v3, acc.y))));
        acc.z = fmaf(a0.z, v0, fmaf(a1.z, v1, fmaf(a2.z, v2, fmaf(a3.z, v3, acc.z))));
        acc.w = fmaf(a0.w, v0, fmaf(a1.w, v1, fmaf(a2.w, v2, fmaf(a3.w, v3, acc.w))));
    }
    for (; t < e2; t++) {
        const int2 p0 = g_spair[t];
        const float v0 = __int_as_float(p0.y);
        const float4 a0 = h4[(size_t)p0.x * 32 + lane];
        acc.x = fmaf(a0.x, v0, acc.x);
        acc.y = fmaf(a0.y, v0, acc.y);
        acc.z = fmaf(a0.z, v0, acc.z);
        acc.w = fmaf(a0.w, v0, acc.w);
    }

    const float4 bv = ((const float4*)b)[lane];
    acc.x = fmaxf(acc.x + bv.x, 0.f);
    acc.y = fmaxf(acc.y + bv.y, 0.f);
    acc.z = fmaxf(acc.z + bv.z, 0.f);
    acc.w = fmaxf(acc.w + bv.w, 0.f);
    out[(size_t)r * 32 + lane] = acc;
}

// ---------------------------------------------------------------------------
extern "C" void kernel_launch(void* const* d_in, const int* in_sizes, int n_in,
                              void* d_out, int out_size) {
    const float* x    = (const float*)d_in[0];   // [N, 128]
    const float* w    = (const float*)d_in[1];   // [128, 128]
    const float* b    = (const float*)d_in[2];   // [128]
    const int*   erow = (const int*)  d_in[3];   // [E]
    const int*   ecol = (const int*)  d_in[4];   // [E]
    const float* evl  = (const float*)d_in[5];   // [E]
    const float* mask = (const float*)d_in[6];   // [N, 128]
    float* out = (float*)d_out;                  // [N, 128]

    float* h;
    cudaGetSymbolAddress((void**)&h, g_h);

    cudaFuncSetAttribute(gemm_mma_kernel,
                         cudaFuncAttributeMaxDynamicSharedMemorySize, SM_TOTAL_G);

    // ---- fork: GEMM path on side stream, CSR build on main stream ----
    cudaEventRecord(g_fj.evFork, 0);
    cudaStreamWaitEvent(g_fj.s2, g_fj.evFork, 0);

    // 1) w prep, then tensor-core GEMM  [side stream]
    wprep_kernel<<<64, 256, 0, g_fj.s2>>>(w);
    gemm_mma_kernel<<<(N_NODES + 127) / 128, 256, SM_TOTAL_G, g_fj.s2>>>(x, mask, h);

    // 2) CSR build  [main stream, concurrent]
    zero_cnt_kernel<<<(N_NODES + 255) / 256, 256>>>();
    hist_kernel<<<(N_EDGES + 255) / 256, 256>>>(erow);
    scan1_kernel<<<NBLK1, SCAN_B>>>();
    scan2_kernel<<<1, 128>>>();
    scan3_kernel<<<(N_NODES + 255) / 256, 256>>>();
    scatter_pairs_kernel<<<(N_EDGES + 255) / 256, 256>>>(erow, ecol, evl);

    // ---- join: agg needs both h and the CSR ----
    cudaEventRecord(g_fj.evJoin, g_fj.s2);
    cudaStreamWaitEvent(0, g_fj.evJoin, 0);

    // 3) aggregate + bias + relu (writes all of d_out)
    agg_kernel<<<(N_NODES + 7) / 8, 256>>>(h, b, (float4*)out);
}

// round 14
// speedup vs baseline: 1.3350x; 1.1235x over previous
#include <cuda_runtime.h>
#include <cuda_fp16.h>
#include <cstdint>

#define N_NODES 100000
#define N_EDGES 1600000
#define D 128

#define SCAN_B 1024
#define NBLK1  ((N_NODES + SCAN_B - 1) / SCAN_B)   // 98

// padded row stride for smem tiles (fp16 elems): conflict-free fragment loads
#define TSTRIDE 136
#define TILE_U4 2304            // 128*136*2B/16 = 2176, padded for copy loop

// ---- static device scratch (no allocs allowed) ----
__device__ __half2 g_hh[(size_t)N_NODES * 64];   // h in fp16 (25.6 MB)
__device__ int   g_cnt[N_NODES];               // histogram, then cursor
__device__ int   g_off[N_NODES + 1];           // CSR row offsets
__device__ int   g_bsum[SCAN_B];               // scan block sums
__device__ int2  g_spair[N_EDGES];             // row-sorted (col, val-bits)
__device__ uint4 g_wT[TILE_U4];                // w^T fp16(rn), padded [128][136]

// ---- host-side stream/event handles (created before harness mem checkpoint) ----
struct ForkJoin {
    cudaStream_t s2;
    cudaEvent_t evFork, evJoin;
    ForkJoin() {
        cudaStreamCreateWithFlags(&s2, cudaStreamNonBlocking);
        cudaEventCreateWithFlags(&evFork, cudaEventDisableTiming);
        cudaEventCreateWithFlags(&evJoin, cudaEventDisableTiming);
    }
};
static ForkJoin g_fj;

// ===========================================================================
// Prep: w -> fp16 (round-nearest), transposed (Bt[n][k] = w[k][n]), padded.
// ===========================================================================
__global__ void wprep_kernel(const float* __restrict__ w) {
    int idx = blockIdx.x * 256 + threadIdx.x;   // 0..16383
    int k = idx >> 7, n = idx & 127;
    ((__half*)g_wT)[n * TSTRIDE + k] = __float2half_rn(w[idx]);
}

// ===========================================================================
// mma.sync fp16 GEMM (single A, single B): h = (x*mask) @ w -> fp16 out
// CTA: 128 rows x 128 cols x K=128. 8 warps in 4x2 grid, warp tile 32x64.
// smem 70KB -> 3 CTAs/SM.
// ===========================================================================
__device__ __forceinline__ void mma16816(float* d, const uint32_t* a, const uint32_t* b) {
    asm volatile(
        "mma.sync.aligned.m16n8k16.row.col.f32.f16.f16.f32 "
        "{%0,%1,%2,%3}, {%4,%5,%6,%7}, {%8,%9}, {%0,%1,%2,%3};"
        : "+f"(d[0]), "+f"(d[1]), "+f"(d[2]), "+f"(d[3])
        : "r"(a[0]), "r"(a[1]), "r"(a[2]), "r"(a[3]), "r"(b[0]), "r"(b[1]));
}

#define SM_A    0
// B region must hold the full padded copy: 2304 uint4 = 36864 bytes
#define SM_B    34816
#define SM_TOTAL_G (34816 + 36864)   // 71680

__global__ __launch_bounds__(256, 3)
void gemm_mma_kernel(const float* __restrict__ x,
                     const float* __restrict__ mask,
                     __half2* __restrict__ hh) {
    extern __shared__ char smem[];
    const int tid = threadIdx.x;
    const int wid = tid >> 5;
    const int lane = tid & 31;
    const int wr = wid >> 1;          // warp row 0..3 -> rows wr*32..+32
    const int wc = wid & 1;           // warp col 0..1 -> cols wc*64..+64
    const int g = lane >> 2;          // group 0..7
    const int t = lane & 3;           // thread-in-group
    const int rowBase = blockIdx.x * 128;

    // ---- B tile: linear copy of prebuilt padded image ----
#pragma unroll
    for (int i = 0; i < 9; i++) {
        int idx = tid + i * 256;      // 0..2303 (tail reads padding)
        ((uint4*)(smem + SM_B))[idx] = g_wT[idx];
    }

    // ---- A tile: load x*mask, fp16 round, store padded row-major ----
#pragma unroll
    for (int i = 0; i < 16; i++) {
        int idx = tid + i * 256;      // 0..4095
        int row = idx >> 5;           // 0..127
        int c4 = (idx & 31) << 2;     // 0,4,...,124
        int grow = rowBase + row;
        float f0 = 0.f, f1 = 0.f, f2 = 0.f, f3 = 0.f;
        if (grow < N_NODES) {
            const float4 xv = *(const float4*)(x    + (size_t)grow * D + c4);
            const float4 mv = *(const float4*)(mask + (size_t)grow * D + c4);
            f0 = xv.x * mv.x; f1 = xv.y * mv.y; f2 = xv.z * mv.z; f3 = xv.w * mv.w;
        }
        int off = (row * TSTRIDE + c4) * 2;       // bytes
        *(__half2*)(smem + SM_A + off)     = __floats2half2_rn(f0, f1);
        *(__half2*)(smem + SM_A + off + 4) = __floats2half2_rn(f2, f3);
    }
    __syncthreads();

    float acc[2][8][4];
#pragma unroll
    for (int mt = 0; mt < 2; mt++)
#pragma unroll
        for (int nt = 0; nt < 8; nt++)
#pragma unroll
            for (int q = 0; q < 4; q++) acc[mt][nt][q] = 0.f;

#pragma unroll
    for (int ks = 0; ks < 8; ks++) {
        const int kb = ks * 16 + 2 * t;           // element col for frag reg 0

        uint32_t af[2][4], bf[8][2];
#pragma unroll
        for (int mt = 0; mt < 2; mt++) {
            const int r = wr * 32 + mt * 16 + g;
            const int o00 = (r * TSTRIDE + kb) * 2;
            const int o10 = ((r + 8) * TSTRIDE + kb) * 2;
            af[mt][0] = *(const uint32_t*)(smem + SM_A + o00);
            af[mt][1] = *(const uint32_t*)(smem + SM_A + o10);
            af[mt][2] = *(const uint32_t*)(smem + SM_A + o00 + 16);
            af[mt][3] = *(const uint32_t*)(smem + SM_A + o10 + 16);
        }
#pragma unroll
        for (int nt = 0; nt < 8; nt++) {
            const int n = wc * 64 + nt * 8 + g;
            const int o = (n * TSTRIDE + kb) * 2;
            bf[nt][0] = *(const uint32_t*)(smem + SM_B + o);
            bf[nt][1] = *(const uint32_t*)(smem + SM_B + o + 16);
        }

#pragma unroll
        for (int mt = 0; mt < 2; mt++)
#pragma unroll
            for (int nt = 0; nt < 8; nt++)
                mma16816(acc[mt][nt], af[mt], bf[nt]);
    }

    // ---- epilogue: fp16 stores (halves downstream gather bytes) ----
#pragma unroll
    for (int mt = 0; mt < 2; mt++) {
        const int r0 = rowBase + wr * 32 + mt * 16 + g;
#pragma unroll
        for (int nt = 0; nt < 8; nt++) {
            const int col2 = wc * 32 + nt * 4 + t;     // half2 index in row (64 per row)
            if (r0 < N_NODES)
                hh[(size_t)r0 * 64 + col2] = __floats2half2_rn(acc[mt][nt][0], acc[mt][nt][1]);
            if (r0 + 8 < N_NODES)
                hh[(size_t)(r0 + 8) * 64 + col2] = __floats2half2_rn(acc[mt][nt][2], acc[mt][nt][3]);
        }
    }
}

// ---------------------------------------------------------------------------
// CSR build: histogram -> scan -> pair scatter
// ---------------------------------------------------------------------------
__global__ void zero_cnt_kernel() {
    int i = blockIdx.x * blockDim.x + threadIdx.x;
    if (i < N_NODES) g_cnt[i] = 0;
}

__global__ void hist_kernel(const int* __restrict__ erow) {
    int e = blockIdx.x * blockDim.x + threadIdx.x;
    if (e < N_EDGES) atomicAdd(&g_cnt[erow[e]], 1);
}

__global__ __launch_bounds__(SCAN_B)
void scan1_kernel() {
    __shared__ int s[SCAN_B];
    int tid = threadIdx.x;
    int gid = blockIdx.x * SCAN_B + tid;
    int v = (gid < N_NODES) ? g_cnt[gid] : 0;
    s[tid] = v;
    __syncthreads();
#pragma unroll
    for (int off = 1; off < SCAN_B; off <<= 1) {
        int t = (tid >= off) ? s[tid - off] : 0;
        __syncthreads();
        s[tid] += t;
        __syncthreads();
    }
    if (gid < N_NODES) g_off[gid] = s[tid] - v;     // exclusive
    if (tid == SCAN_B - 1) g_bsum[blockIdx.x] = s[tid];
}

__global__ __launch_bounds__(128)
void scan2_kernel() {
    __shared__ int s[128];
    int tid = threadIdx.x;
    int v = (tid < NBLK1) ? g_bsum[tid] : 0;
    s[tid] = v;
    __syncthreads();
#pragma unroll
    for (int off = 1; off < 128; off <<= 1) {
        int t = (tid >= off) ? s[tid - off] : 0;
        __syncthreads();
        s[tid] += t;
        __syncthreads();
    }
    g_bsum[tid] = s[tid] - v;                       // exclusive
}

__global__ void scan3_kernel() {
    int i = blockIdx.x * blockDim.x + threadIdx.x;
    if (i < N_NODES) {
        g_off[i] += g_bsum[i >> 10];
        g_cnt[i] = 0;
    }
    if (i == 0) g_off[N_NODES] = N_EDGES;
}

__global__ void scatter_pairs_kernel(const int* __restrict__ erow,
                                     const int* __restrict__ ecol,
                                     const float* __restrict__ evl) {
    int e = blockIdx.x * blockDim.x + threadIdx.x;
    if (e >= N_EDGES) return;
    int r = erow[e];
    int p = g_off[r] + atomicAdd(&g_cnt[r], 1);
    g_spair[p] = make_int2(ecol[e], __float_as_int(evl[e]));
}

// ---------------------------------------------------------------------------
// Aggregation: warp per row, fp16 gather (256B/edge) + fp32 accumulate,
// fused bias+relu; writes d_out exactly once. Unroll x4 for MLP.
// ---------------------------------------------------------------------------
__device__ __forceinline__ void acc_edge(float4& acc, const uint2 u, const float v) {
    const float2 f0 = __half22float2(*(const __half2*)&u.x);
    const float2 f1 = __half22float2(*(const __half2*)&u.y);
    acc.x = fmaf(f0.x, v, acc.x);
    acc.y = fmaf(f0.y, v, acc.y);
    acc.z = fmaf(f1.x, v, acc.z);
    acc.w = fmaf(f1.y, v, acc.w);
}

__global__ __launch_bounds__(256)
void agg_kernel(const __half2* __restrict__ hh,
                const float* __restrict__ b,
                float4* __restrict__ out) {
    const int r = blockIdx.x * 8 + (threadIdx.x >> 5);
    const int lane = threadIdx.x & 31;
    if (r >= N_NODES) return;

    const int s  = g_off[r];
    const int e2 = g_off[r + 1];
    const uint2* __restrict__ h8 = (const uint2*)hh;   // 4 halves per lane

    float4 acc = make_float4(0.f, 0.f, 0.f, 0.f);
    int t = s;
    for (; t + 3 < e2; t += 4) {
        const int2 p0 = g_spair[t];
        const int2 p1 = g_spair[t + 1];
        const int2 p2 = g_spair[t + 2];
        const int2 p3 = g_spair[t + 3];
        const uint2 a0 = h8[(size_t)p0.x * 32 + lane];
        const uint2 a1 = h8[(size_t)p1.x * 32 + lane];
        const uint2 a2 = h8[(size_t)p2.x * 32 + lane];
        const uint2 a3 = h8[(size_t)p3.x * 32 + lane];
        acc_edge(acc, a0, __int_as_float(p0.y));
        acc_edge(acc, a1, __int_as_float(p1.y));
        acc_edge(acc, a2, __int_as_float(p2.y));
        acc_edge(acc, a3, __int_as_float(p3.y));
    }
    for (; t < e2; t++) {
        const int2 p0 = g_spair[t];
        const uint2 a0 = h8[(size_t)p0.x * 32 + lane];
        acc_edge(acc, a0, __int_as_float(p0.y));
    }

    const float4 bv = ((const float4*)b)[lane];
    acc.x = fmaxf(acc.x + bv.x, 0.f);
    acc.y = fmaxf(acc.y + bv.y, 0.f);
    acc.z = fmaxf(acc.z + bv.z, 0.f);
    acc.w = fmaxf(acc.w + bv.w, 0.f);
    out[(size_t)r * 32 + lane] = acc;
}

// ---------------------------------------------------------------------------
extern "C" void kernel_launch(void* const* d_in, const int* in_sizes, int n_in,
                              void* d_out, int out_size) {
    const float* x    = (const float*)d_in[0];   // [N, 128]
    const float* w    = (const float*)d_in[1];   // [128, 128]
    const float* b    = (const float*)d_in[2];   // [128]
    const int*   erow = (const int*)  d_in[3];   // [E]
    const int*   ecol = (const int*)  d_in[4];   // [E]
    const float* evl  = (const float*)d_in[5];   // [E]
    const float* mask = (const float*)d_in[6];   // [N, 128]
    float* out = (float*)d_out;                  // [N, 128]

    __half2* hh;
    cudaGetSymbolAddress((void**)&hh, g_hh);

    cudaFuncSetAttribute(gemm_mma_kernel,
                         cudaFuncAttributeMaxDynamicSharedMemorySize, SM_TOTAL_G);

    // ---- fork: GEMM path on side stream, CSR build on main stream ----
    cudaEventRecord(g_fj.evFork, 0);
    cudaStreamWaitEvent(g_fj.s2, g_fj.evFork, 0);

    // 1) w prep, then tensor-core GEMM  [side stream]
    wprep_kernel<<<64, 256, 0, g_fj.s2>>>(w);
    gemm_mma_kernel<<<(N_NODES + 127) / 128, 256, SM_TOTAL_G, g_fj.s2>>>(x, mask, hh);

    // 2) CSR build  [main stream, concurrent]
    zero_cnt_kernel<<<(N_NODES + 255) / 256, 256>>>();
    hist_kernel<<<(N_EDGES + 255) / 256, 256>>>(erow);
    scan1_kernel<<<NBLK1, SCAN_B>>>();
    scan2_kernel<<<1, 128>>>();
    scan3_kernel<<<(N_NODES + 255) / 256, 256>>>();
    scatter_pairs_kernel<<<(N_EDGES + 255) / 256, 256>>>(erow, ecol, evl);

    // ---- join: agg needs both h and the CSR ----
    cudaEventRecord(g_fj.evJoin, g_fj.s2);
    cudaStreamWaitEvent(0, g_fj.evJoin, 0);

    // 3) aggregate + bias + relu (writes all of d_out)
    agg_kernel<<<(N_NODES + 7) / 8, 256>>>(hh, b, (float4*)out);
}